// round 2
// baseline (speedup 1.0000x reference)
#include <cuda_runtime.h>
#include <math.h>

#define NMAX 50000
#define HID  32
#define DIN  128

// ---------------- scratch (static allocation; no cudaMalloc allowed) ----------------
__device__ __align__(128) float g_y1[NMAX * HID];    // x @ W1_l.T
__device__ __align__(128) float g_r1[NMAX * HID];    // x @ W1_r.T
__device__ __align__(128) float g_agg1[NMAX * HID];  // segment sum of y1 over edges
__device__ __align__(128) float g_deg[NMAX];
__device__ __align__(128) float g_z2[NMAX];          // h @ W2_l.T (scalar)
__device__ __align__(128) float g_r2[NMAX];          // h @ W2_r.T (scalar)
__device__ __align__(128) float g_agg2[NMAX];
__device__ int g_is64;

// ---------------- packed f32x2 helpers ----------------
__device__ __forceinline__ unsigned long long fma2(unsigned long long a,
                                                   unsigned long long b,
                                                   unsigned long long c) {
    unsigned long long d;
    asm("fma.rn.f32x2 %0, %1, %2, %3;" : "=l"(d) : "l"(a), "l"(b), "l"(c));
    return d;
}
__device__ __forceinline__ float hsum2(unsigned long long a) {
    float lo, hi;
    asm("mov.b64 {%0, %1}, %2;" : "=f"(lo), "=f"(hi) : "l"(a));
    return lo + hi;
}

__device__ __forceinline__ void red_add_v4(float* addr, float4 v) {
    asm volatile("red.global.add.v4.f32 [%0], {%1, %2, %3, %4};"
                 :: "l"(addr), "f"(v.x), "f"(v.y), "f"(v.z), "f"(v.w)
                 : "memory");
}

__device__ __forceinline__ void load_edge(const void* ei, int E, int e, int is64,
                                          int& s, int& d) {
    if (is64) {
        const long long* p = (const long long*)ei;
        s = (int)p[e];
        d = (int)p[E + e];
    } else {
        const int* p = (const int*)ei;
        s = p[e];
        d = p[E + e];
    }
}

// ---------------- kernel 1: zero scratch + edge dtype detection ----------------
// int64 detection: node ids < 2^31, so with little-endian int64 every odd int32
// word of the edge buffer is 0.
__global__ void k_zero(const unsigned int* ei32, int n) {
    if (blockIdx.x == 0) {
        __shared__ int found;
        if (threadIdx.x == 0) found = 0;
        __syncthreads();
        for (int i = 1 + 2 * threadIdx.x; i < 4096; i += 2 * blockDim.x)
            if (ei32[i] != 0u) found = 1;  // benign race
        __syncthreads();
        if (threadIdx.x == 0) g_is64 = (found == 0) ? 1 : 0;
    }
    int tot = n * HID;
    int stride = gridDim.x * blockDim.x;
    for (int i = blockIdx.x * blockDim.x + threadIdx.x; i < tot; i += stride)
        g_agg1[i] = 0.0f;
    for (int i = blockIdx.x * blockDim.x + threadIdx.x; i < n; i += stride) {
        g_deg[i] = 0.0f;
        g_agg2[i] = 0.0f;
    }
}

// ---------------- kernel 2: fused projections with register-resident weights ----
// 128 threads/block. Thread t owns output o = t&63 (o<32 -> W1_l row o,
// o>=32 -> W1_r row o-32) and K-half h = t>>6. 64 weight floats live in
// registers as 32 f32x2 pairs. x is staged 8 nodes at a time in smem and read
// back as warp-broadcast LDS.128 (all lanes of a warp share h -> same address).
#define NB 8
__global__ void __launch_bounds__(128) k_lin1(const float* __restrict__ x,
                                              const float* __restrict__ Wl,
                                              const float* __restrict__ Wr,
                                              int n) {
    __shared__ __align__(16) float sx[NB * DIN];       // 4 KB x tile
    __shared__ float sp[NB * 64];                      // 2 KB partials (h=1)

    int t = threadIdx.x;
    int o = t & 63;
    int h = t >> 6;

    // load this thread's 64 weight floats into registers
    const float* wrow = (o < 32) ? (Wl + o * DIN) : (Wr + (o - 32) * DIN);
    wrow += h * 64;
    ulonglong2 wreg[16];
#pragma unroll
    for (int j = 0; j < 16; j++)
        wreg[j] = ((const ulonglong2*)wrow)[j];

    const float4* x4 = (const float4*)x;
    int nbatch = (n + NB - 1) / NB;

    for (int b = blockIdx.x; b < nbatch; b += gridDim.x) {
        int nb0 = b * NB;
        // stage x tile: NB*32 float4 = 256, 2 per thread
#pragma unroll
        for (int i = 0; i < 2; i++) {
            int idx = t + i * 128;            // 0..255
            int nn = idx >> 5, k4 = idx & 31;
            float4 v = make_float4(0.f, 0.f, 0.f, 0.f);
            if (nb0 + nn < n) v = x4[(nb0 + nn) * 32 + k4];
            ((float4*)sx)[idx] = v;
        }
        __syncthreads();

        float sum[NB];
#pragma unroll
        for (int nn = 0; nn < NB; nn++) {
            const ulonglong2* xp = (const ulonglong2*)(sx + nn * DIN + h * 64);
            unsigned long long aA = 0ull, aB = 0ull;
#pragma unroll
            for (int j = 0; j < 16; j++) {
                ulonglong2 xv = xp[j];        // broadcast LDS.128
                aA = fma2(xv.x, wreg[j].x, aA);
                aB = fma2(xv.y, wreg[j].y, aB);
            }
            sum[nn] = hsum2(aA) + hsum2(aB);
        }

        if (h == 1) {
#pragma unroll
            for (int nn = 0; nn < NB; nn++) sp[nn * 64 + o] = sum[nn];
        }
        __syncthreads();
        if (h == 0) {
#pragma unroll
            for (int nn = 0; nn < NB; nn++) {
                int node = nb0 + nn;
                if (node < n) {
                    float v = sum[nn] + sp[nn * 64 + o];
                    if (o < 32) g_y1[node * 32 + o] = v;
                    else        g_r1[node * 32 + (o - 32)] = v;
                }
            }
        }
        // next iteration's __syncthreads (after the x-tile store) orders the
        // sp reads above against the next batch's sp writes.
    }
}

// ---------------- kernel 3: edge aggregation of y1 (32-dim) + degree ----------------
// 4 threads per edge, each owning two float4 chunks -> 2 independent
// gather->RED chains per thread for latency hiding.
__global__ void k_edge1(const void* __restrict__ ei, int E) {
    int is64 = g_is64;
    int total = E * 4;
    int stride = gridDim.x * blockDim.x;
    for (int t = blockIdx.x * blockDim.x + threadIdx.x; t < total; t += stride) {
        int e = t >> 2, c = t & 3;
        int s, d;
        load_edge(ei, E, e, is64, s, d);
        float4 v0 = ((const float4*)g_y1)[s * 8 + c];
        float4 v1 = ((const float4*)g_y1)[s * 8 + c + 4];
        red_add_v4(&g_agg1[d * 32 + c * 4], v0);
        red_add_v4(&g_agg1[d * 32 + (c + 4) * 4], v1);
        if (c == 0) atomicAdd(&g_deg[d], 1.0f);
    }
}

// ---------------- kernel 4: node update h=relu(...) fused with layer-2 projections ----
__global__ void __launch_bounds__(128) k_node1(const float* __restrict__ b1,
                                               const float* __restrict__ W2l,
                                               const float* __restrict__ W2r,
                                               int n) {
    int tid = threadIdx.x;
    int warp = tid >> 5, lane = tid & 31;
    int stride = gridDim.x * 4;
    for (int node = blockIdx.x * 4 + warp; node < n; node += stride) {
        float inv = 1.0f / fmaxf(g_deg[node], 1.0f);
        float h = fmaf(g_agg1[node * 32 + lane], inv,
                       b1[lane] + g_r1[node * 32 + lane]);
        h = fmaxf(h, 0.0f);
        float zl = h * W2l[lane];
        float zr = h * W2r[lane];
#pragma unroll
        for (int o = 16; o; o >>= 1) {
            zl += __shfl_xor_sync(0xFFFFFFFFu, zl, o);
            zr += __shfl_xor_sync(0xFFFFFFFFu, zr, o);
        }
        if (lane == 0) {
            g_z2[node] = zl;
            g_r2[node] = zr;
        }
    }
}

// ---------------- kernel 5: scalar edge aggregation of z2 ----------------
__global__ void k_edge2(const void* __restrict__ ei, int E) {
    int is64 = g_is64;
    int stride = gridDim.x * blockDim.x;
    for (int e = blockIdx.x * blockDim.x + threadIdx.x; e < E; e += stride) {
        int s, d;
        load_edge(ei, E, e, is64, s, d);
        atomicAdd(&g_agg2[d], g_z2[s]);
    }
}

// ---------------- kernel 6: final sigmoid ----------------
__global__ void k_out(float* __restrict__ out, const float* __restrict__ b2, int n) {
    int i = blockIdx.x * blockDim.x + threadIdx.x;
    if (i < n) {
        float inv = 1.0f / fmaxf(g_deg[i], 1.0f);
        float v = fmaf(g_agg2[i], inv, b2[0] + g_r2[i]);
        out[i] = 1.0f / (1.0f + expf(-v));
    }
}

// ---------------- launch ----------------
extern "C" void kernel_launch(void* const* d_in, const int* in_sizes, int n_in,
                              void* d_out, int out_size) {
    const float* x   = (const float*)d_in[0];
    const void*  ei  = d_in[1];
    const float* W1l = (const float*)d_in[2];
    const float* b1  = (const float*)d_in[3];
    const float* W1r = (const float*)d_in[4];
    const float* W2l = (const float*)d_in[5];
    const float* b2  = (const float*)d_in[6];
    const float* W2r = (const float*)d_in[7];
    float* out = (float*)d_out;

    int n = in_sizes[0] / DIN;
    int E = in_sizes[1] / 2;
    if (n > NMAX) n = NMAX;

    k_zero<<<2048, 256>>>((const unsigned int*)ei, n);
    k_lin1<<<888, 128>>>(x, W1l, W1r, n);
    k_edge1<<<(E * 4 + 255) / 256, 256>>>(ei, E);
    k_node1<<<(n + 3) / 4, 128>>>(b1, W2l, W2r, n);
    k_edge2<<<(E + 255) / 256, 256>>>(ei, E);
    k_out<<<(n + 255) / 256, 256>>>(out, b2, n);
}